// round 15
// baseline (speedup 1.0000x reference)
#include <cuda_runtime.h>
#include <cuda_fp16.h>
#include <math.h>

#define BB 8
#define CC 32
#define NC2 (CC/2)      /* 16 channel pairs */
#define HH 120
#define WW 160
#define HW (HH*WW)
#define CHW (CC*HW)
#define OUT_ROW (12 + CHW)
#define NBLK (HW/256)   /* 75 */
#define OCC_THRES 0.1f

// channel-pair tap: {f1_c0, jf_c0(bits), f1_c1, jf_c1(bits)} = 16 B, one LDG.128
// serves two channels at one pixel.
typedef float4 Tap2;

__device__ __forceinline__ float2 jf_of(float bits) {
    __half2 h = *reinterpret_cast<__half2*>(&bits);
    return __half22float2(h);
}

// ---------------- static device state (no dynamic allocation) ----------------
__device__ Tap2  g_tap2[BB*NC2*HW];
__device__ float g_R[BB][9];
__device__ float g_t[BB][3];
__device__ float g_part[BB][NBLK][27];
__device__ int   g_cnt[3][BB];   // zero-init; self-resetting per replay

// ------- Sobel (8 px x 2 ch per thread) + F1 interleave + pose init ----------
__global__ void sobel_kernel(const float* __restrict__ F1,
                             const float* __restrict__ Rin,
                             const float* __restrict__ tin) {
    if (blockIdx.x == 0) {
        int i = threadIdx.x;
        if (i < 72) g_R[i/9][i%9] = Rin[i];
        if (i < 24) g_t[i/3][i%3] = tin[i];
    }
    const int g = blockIdx.x*blockDim.x + threadIdx.x;   // per (b, c2, 8-px group)
    if (g >= BB*NC2*(HW/8)) return;
    const int pg = g % (HW/8);
    const int c2 = (g / (HW/8)) % NC2;
    const int b  = g / ((HW/8)*NC2);
    const int i8 = pg * 8;
    const int x  = i8 % WW;                               // multiple of 8
    const int y  = i8 / WW;

    const int ym = max(y-1,0)*WW, y0r = y*WW, yp = min(y+1,HH-1)*WW;
    const int xl = max(x-1,0), xr = min(x+8, WW-1);

    float f1v[2][8]; float jfb[2][8];
    #pragma unroll
    for (int j = 0; j < 2; ++j) {
        const float* F = F1 + (size_t)(b*CC + c2*2 + j)*HW;
        float rm[10], r0[10], rp[10];
        {
            float4 a0 = *(const float4*)(F + ym  + x);
            float4 a1 = *(const float4*)(F + ym  + x + 4);
            rm[0]=F[ym+xl]; rm[1]=a0.x; rm[2]=a0.y; rm[3]=a0.z; rm[4]=a0.w;
            rm[5]=a1.x; rm[6]=a1.y; rm[7]=a1.z; rm[8]=a1.w; rm[9]=F[ym+xr];
            float4 b0 = *(const float4*)(F + y0r + x);
            float4 b1 = *(const float4*)(F + y0r + x + 4);
            r0[0]=F[y0r+xl]; r0[1]=b0.x; r0[2]=b0.y; r0[3]=b0.z; r0[4]=b0.w;
            r0[5]=b1.x; r0[6]=b1.y; r0[7]=b1.z; r0[8]=b1.w; r0[9]=F[y0r+xr];
            float4 c0 = *(const float4*)(F + yp  + x);
            float4 c1 = *(const float4*)(F + yp  + x + 4);
            rp[0]=F[yp+xl]; rp[1]=c0.x; rp[2]=c0.y; rp[3]=c0.z; rp[4]=c0.w;
            rp[5]=c1.x; rp[6]=c1.y; rp[7]=c1.z; rp[8]=c1.w; rp[9]=F[yp+xr];
        }
        #pragma unroll
        for (int k = 0; k < 8; ++k) {
            const float dx = (rm[k+2]-rm[k]) + 2.0f*(r0[k+2]-r0[k]) + (rp[k+2]-rp[k]);
            const float dy = (rp[k]-rm[k]) + 2.0f*(rp[k+1]-rm[k+1]) + (rp[k+2]-rm[k+2]);
            const float inv_mag = rsqrtf(dx*dx + dy*dy + 1e-8f);
            __half2 h = __floats2half2_rn(dx*inv_mag, dy*inv_mag);
            jfb[j][k] = __uint_as_float(*reinterpret_cast<unsigned*>(&h));
            f1v[j][k] = r0[k+1];
        }
    }
    Tap2* D = g_tap2 + (size_t)(b*NC2 + c2)*HW + i8;
    #pragma unroll
    for (int k = 0; k < 8; ++k)
        D[k] = make_float4(f1v[0][k], jfb[0][k], f1v[1][k], jfb[1][k]);
}

// ----- fused per-pixel accumulation + last-block reduction/solve -------------
__global__ void __launch_bounds__(256)
accum_kernel(const float* __restrict__ F0, const float* __restrict__ invD0,
             const float* __restrict__ invD1, const float* __restrict__ Kmat,
             float* __restrict__ out, int it)
{
    const int  b    = blockIdx.y;
    const int  last = (it == 2);
    const int  pix  = blockIdx.x*blockDim.x + threadIdx.x;   // 0..19199 exactly
    const int  x    = pix % WW;
    const int  y    = pix / WW;

    // pose + intrinsics (broadcast loads)
    const float R0=g_R[b][0], R1=g_R[b][1], R2=g_R[b][2];
    const float R3=g_R[b][3], R4=g_R[b][4], R5=g_R[b][5];
    const float R6=g_R[b][6], R7=g_R[b][7], R8=g_R[b][8];
    const float t0=g_t[b][0], t1=g_t[b][1], t2=g_t[b][2];
    const float fx=Kmat[b*4+0], fy=Kmat[b*4+1], cx=Kmat[b*4+2], cy=Kmat[b*4+3];

    const float px = ((float)x - cx) / fx;
    const float py = ((float)y - cy) / fy;
    const float id0 = invD0[(size_t)b*HW + pix];

    // warp inverse depth: warped = R*[px,py,1] + t*invD0
    const float X = R0*px + R1*py + R2 + t0*id0;
    const float Y = R3*px + R4*py + R5 + t1*id0;
    const float S = R6*px + R7*py + R8 + t2*id0;
    const float u = (X/S)*fx + cx;
    const float v = (Y/S)*fy + cy;
    const float inv_z = id0 / S;

    const bool inview = (u > 0.0f) && (u < (float)(WW-1)) &&
                        (v > 0.0f) && (v < (float)(HH-1));

    // clipped bilinear setup
    const float uc = fminf(fmaxf(u, 0.0f), (float)(WW-1));
    const float vc = fminf(fmaxf(v, 0.0f), (float)(HH-1));
    const float x0f = floorf(uc), y0f = floorf(vc);
    const float wx = uc - x0f,  wy = vc - y0f;
    const int x0 = (int)x0f, y0 = (int)y0f;
    const int x1 = min(x0+1, WW-1), y1 = min(y0+1, HH-1);
    const int i00 = y0*WW+x0, i01 = y0*WW+x1, i10 = y1*WW+x0, i11 = y1*WW+x1;
    const float w00 = (1.0f-wx)*(1.0f-wy), w01 = wx*(1.0f-wy);
    const float w10 = (1.0f-wx)*wy,        w11 = wx*wy;

    // occlusion (invD1 warp, single channel)
    const float* D1 = invD1 + (size_t)b*HW;
    const float invD1w = D1[i00]*w00 + D1[i01]*w01 + D1[i10]*w10 + D1[i11]*w11;
    const bool occ = !((inv_z > invD1w - OCC_THRES) && inview);

    // jacobian warp: warped = R*[px,py,invD0] + t
    const float xj = R0*px + R1*py + R2*id0 + t0;
    const float yj = R3*px + R4*py + R5*id0 + t1;
    const float iz = R6*px + R7*py + R8*id0 + t2;
    const float Jx[6] = { fx*(-xj*yj), fx*(1.0f+xj*xj), fx*(-yj),
                          fx*iz,       0.0f,            fx*(-iz*xj) };
    const float Jy[6] = { fy*(-1.0f-yj*yj), fy*(xj*yj), fy*xj,
                          0.0f,             fy*iz,      fy*(-iz*yj) };

    // channel-pair loop -> 5 scalar sums (arithmetic identical to R11)
    float saa = 0.f, sab = 0.f, sbb = 0.f, sar = 0.f, sbr = 0.f;
    const float* F0b = F0     + (size_t)b*CHW;
    const Tap2*  Tb  = g_tap2 + (size_t)b*NC2*HW;

    #pragma unroll 2
    for (int c2 = 0; c2 < NC2; ++c2) {
        const Tap2* T2 = Tb + (size_t)c2*HW;
        const Tap2 q00 = T2[i00];
        const Tap2 q01 = T2[i01];
        const Tap2 q10 = T2[i10];
        const Tap2 q11 = T2[i11];
        #pragma unroll
        for (int j = 0; j < 2; ++j) {
            const int o = (c2*2 + j)*HW;
            const float f00 = j ? q00.z : q00.x,  b00 = j ? q00.w : q00.y;
            const float f01 = j ? q01.z : q01.x,  b01 = j ? q01.w : q01.y;
            const float f10 = j ? q10.z : q10.x,  b10 = j ? q10.w : q10.y;
            const float f11 = j ? q11.z : q11.x,  b11 = j ? q11.w : q11.y;
            const float f1w = f00*w00 + f01*w01 + f10*w10 + f11*w11;
            const float2 g00 = jf_of(b00);
            const float2 g01 = jf_of(b01);
            const float2 g10 = jf_of(b10);
            const float2 g11 = jf_of(b11);
            const float ax = g00.x*w00 + g01.x*w01 + g10.x*w10 + g11.x*w11;
            const float ay = g00.y*w00 + g01.y*w01 + g10.y*w10 + g11.y*w11;
            const float r   = occ ? 0.001f : (f1w - F0b[o + pix]);
            const float wgt = __fdividef(1.0f, 1.0f + r*r);
            const float wr  = wgt * r;
            saa += ax*ax;  sab += ax*ay;  sbb += ay*ay;
            sar += ax*wr;  sbr += ay*wr;
            if (last) __stwt(&out[(size_t)b*OUT_ROW + 12 + o + pix], wgt);
        }
    }

    // per-pixel contribution: rank-2 factorized outer product (21) + rhs (6)
    float acc[27];
    {
        float A6[6], B6[6];
        #pragma unroll
        for (int l = 0; l < 6; ++l) {
            A6[l] = saa*Jx[l] + sab*Jy[l];
            B6[l] = sab*Jx[l] + sbb*Jy[l];
        }
        int idx = 0;
        #pragma unroll
        for (int k = 0; k < 6; ++k)
            #pragma unroll
            for (int l = k; l < 6; ++l)
                acc[idx++] = Jx[k]*A6[l] + Jy[k]*B6[l];
        #pragma unroll
        for (int k = 0; k < 6; ++k)
            acc[idx++] = -(sar*Jx[k] + sbr*Jy[k]);
    }

    // deterministic block reduction: warp shuffle -> smem -> single partial
    #pragma unroll
    for (int j = 0; j < 27; ++j) {
        float s = acc[j];
        #pragma unroll
        for (int off = 16; off > 0; off >>= 1)
            s += __shfl_down_sync(0xffffffffu, s, off);
        acc[j] = s;
    }
    __shared__ float sm[8][27];
    const int warp = threadIdx.x >> 5, lane = threadIdx.x & 31;
    if (lane == 0) {
        #pragma unroll
        for (int j = 0; j < 27; ++j) sm[warp][j] = acc[j];
    }
    __syncthreads();
    if (threadIdx.x < 27) {
        float s = 0.f;
        #pragma unroll
        for (int wp = 0; wp < 8; ++wp) s += sm[wp][threadIdx.x];
        g_part[b][blockIdx.x][threadIdx.x] = s;
    }

    // ---------- last-arriving block for this batch does reduce + solve -------
    __syncthreads();                       // g_part stores complete block-wide
    __shared__ int amLast;
    __threadfence();                       // publish g_part slice
    if (threadIdx.x == 0)
        amLast = (atomicAdd(&g_cnt[it][b], 1) == NBLK - 1);
    __syncthreads();
    if (!amLast) return;
    __threadfence();                       // acquire other blocks' g_part

    __shared__ float red[27];
    if (threadIdx.x < 27) {
        double s0 = 0.0, s1 = 0.0, s2 = 0.0, s3 = 0.0, s4 = 0.0;
        #pragma unroll
        for (int i = 0; i < 15; ++i) {
            s0 += (double)g_part[b][i     ][threadIdx.x];
            s1 += (double)g_part[b][i + 15][threadIdx.x];
            s2 += (double)g_part[b][i + 30][threadIdx.x];
            s3 += (double)g_part[b][i + 45][threadIdx.x];
            s4 += (double)g_part[b][i + 60][threadIdx.x];
        }
        red[threadIdx.x] = (float)(((s0 + s1) + (s2 + s3)) + s4);
    }
    __syncthreads();
    if (threadIdx.x != 0) return;

    g_cnt[it][b] = 0;                      // reset for next graph replay

    // assemble SPD A (+damping) and rhs  (fp32)
    float A[6][6], rhs[6];
    {
        int idx = 0;
        #pragma unroll
        for (int k = 0; k < 6; ++k)
            #pragma unroll
            for (int l = 0; l < 6; ++l) if (l >= k) { A[k][l] = red[idx]; A[l][k] = red[idx]; ++idx; }
        #pragma unroll
        for (int k = 0; k < 6; ++k) A[k][k] += 1e-4f;
        #pragma unroll
        for (int i = 0; i < 6; ++i) rhs[i] = red[21+i];
    }

    // Cholesky A = L L^T (SPD, no pivoting) — accurate fp32 ops
    float L[6][6];
    #pragma unroll
    for (int j = 0; j < 6; ++j) {
        float d = A[j][j];
        #pragma unroll
        for (int k = 0; k < 6; ++k) if (k < j) d -= L[j][k]*L[j][k];
        const float ljj = sqrtf(d);
        const float inv_ljj = 1.0f / ljj;
        L[j][j] = ljj;
        #pragma unroll
        for (int i = 0; i < 6; ++i) if (i > j) {
            float s = A[i][j];
            #pragma unroll
            for (int k = 0; k < 6; ++k) if (k < j) s -= L[i][k]*L[j][k];
            L[i][j] = s * inv_ljj;
        }
    }
    // forward/back substitution
    float yv[6], dp[6];
    #pragma unroll
    for (int i = 0; i < 6; ++i) {
        float s = rhs[i];
        #pragma unroll
        for (int k = 0; k < 6; ++k) if (k < i) s -= L[i][k]*yv[k];
        yv[i] = s / L[i][i];
    }
    #pragma unroll
    for (int i = 5; i >= 0; --i) {
        float s = yv[i];
        #pragma unroll
        for (int k = 0; k < 6; ++k) if (k > i) s -= L[k][i]*dp[k];
        dp[i] = s / L[i][i];
    }

    // se3 exponential (fp32, accurate sincosf/sqrtf)
    const float w0 = dp[0], w1 = dp[1], w2 = dp[2];
    const float v0 = dp[3], v1 = dp[4], v2 = dp[5];
    const float th2  = w0*w0 + w1*w1 + w2*w2;
    const float th2e = th2 + 1e-12f;
    const float th   = sqrtf(th2e);
    float sth, cth;
    sincosf(th, &sth, &cth);
    const float a   = sth / th;
    const float bbv = (1.0f - cth) / th2e;
    const float ccv = (1.0f - a) / th2e;
    const float Wm[3][3] = { {0.0f, -w2,  w1},
                             {w2,  0.0f, -w0},
                             {-w1, w0,  0.0f} };
    float W2[3][3];
    #pragma unroll
    for (int i = 0; i < 3; ++i)
        #pragma unroll
        for (int j = 0; j < 3; ++j)
            W2[i][j] = Wm[i][0]*Wm[0][j] + Wm[i][1]*Wm[1][j] + Wm[i][2]*Wm[2][j];
    float dR[3][3], Vm[3][3];
    #pragma unroll
    for (int i = 0; i < 3; ++i)
        #pragma unroll
        for (int j = 0; j < 3; ++j) {
            const float I = (i == j) ? 1.0f : 0.0f;
            dR[i][j] = I + a  * Wm[i][j] + bbv * W2[i][j];
            Vm[i][j] = I + bbv* Wm[i][j] + ccv * W2[i][j];
        }
    const float dt0 = Vm[0][0]*v0 + Vm[0][1]*v1 + Vm[0][2]*v2;
    const float dt1 = Vm[1][0]*v0 + Vm[1][1]*v1 + Vm[1][2]*v2;
    const float dt2 = Vm[2][0]*v0 + Vm[2][1]*v1 + Vm[2][2]*v2;

    // pose update: t = dR*t + dt ; R = dR*R
    float Rold[9], told[3];
    #pragma unroll
    for (int i = 0; i < 9; ++i) Rold[i] = g_R[b][i];
    #pragma unroll
    for (int i = 0; i < 3; ++i) told[i] = g_t[b][i];

    float tnew[3], Rnew[9];
    #pragma unroll
    for (int i = 0; i < 3; ++i) {
        tnew[i] = dR[i][0]*told[0] + dR[i][1]*told[1] + dR[i][2]*told[2]
                + ((i==0)?dt0:(i==1)?dt1:dt2);
        #pragma unroll
        for (int j = 0; j < 3; ++j)
            Rnew[i*3+j] = dR[i][0]*Rold[0*3+j] + dR[i][1]*Rold[1*3+j] + dR[i][2]*Rold[2*3+j];
    }
    #pragma unroll
    for (int i = 0; i < 9; ++i) g_R[b][i] = Rnew[i];
    #pragma unroll
    for (int i = 0; i < 3; ++i) g_t[b][i] = tnew[i];

    if (last) {
        #pragma unroll
        for (int i = 0; i < 9; ++i) out[(size_t)b*OUT_ROW + i]     = Rnew[i];
        #pragma unroll
        for (int i = 0; i < 3; ++i) out[(size_t)b*OUT_ROW + 9 + i] = tnew[i];
    }
}

// ---------------- launch ------------------------------------------------------
extern "C" void kernel_launch(void* const* d_in, const int* in_sizes, int n_in,
                              void* d_out, int out_size) {
    const float* R     = (const float*)d_in[0];
    const float* t     = (const float*)d_in[1];
    const float* F0    = (const float*)d_in[2];
    const float* F1    = (const float*)d_in[3];
    const float* invD0 = (const float*)d_in[4];
    const float* invD1 = (const float*)d_in[5];
    const float* K     = (const float*)d_in[6];
    float* out = (float*)d_out;

    const int nth = BB*NC2*(HW/8);
    sobel_kernel<<<(nth + 255)/256, 256>>>(F1, R, t);

    for (int it = 0; it < 3; ++it)
        accum_kernel<<<dim3(NBLK, BB), 256>>>(F0, invD0, invD1, K, out, it);
}

// round 16
// speedup vs baseline: 1.1134x; 1.1134x over previous
#include <cuda_runtime.h>
#include <cuda_fp16.h>
#include <math.h>

#define BB 8
#define CC 32
#define NC2 (CC/2)      /* 16 channel pairs */
#define HH 120
#define WW 160
#define HW (HH*WW)
#define CHW (CC*HW)
#define OUT_ROW (12 + CHW)
#define NBLK (HW/256)   /* 75 */
#define OCC_THRES 0.1f

// channel-pair tap: {f1_c0, jf_c0(bits), f1_c1, jf_c1(bits)} = 16 B, one LDG.128
// serves two channels at one pixel.
typedef float4 Tap2;

__device__ __forceinline__ float2 jf_of(float bits) {
    __half2 h = *reinterpret_cast<__half2*>(&bits);
    return __half22float2(h);
}

// ---------------- static device state (no dynamic allocation) ----------------
__device__ Tap2  g_tap2[BB*NC2*HW];
__device__ float g_R[BB][9];
__device__ float g_t[BB][3];
__device__ float g_part[BB][NBLK][27];
__device__ int   g_cnt[3][BB];   // zero-init; self-resetting per replay

// ------- Sobel (4 px x 2 ch per thread) + F1 interleave + pose init ----------
__global__ void sobel_kernel(const float* __restrict__ F1,
                             const float* __restrict__ Rin,
                             const float* __restrict__ tin) {
    if (blockIdx.x == 0) {
        int i = threadIdx.x;
        if (i < 72) g_R[i/9][i%9] = Rin[i];
        if (i < 24) g_t[i/3][i%3] = tin[i];
    }
    const int g = blockIdx.x*blockDim.x + threadIdx.x;   // per (b, c2, 4-px group)
    if (g >= BB*NC2*(HW/4)) return;
    const int pg = g % (HW/4);
    const int c2 = (g / (HW/4)) % NC2;
    const int b  = g / ((HW/4)*NC2);
    const int i4 = pg * 4;
    const int x  = i4 % WW;                               // multiple of 4
    const int y  = i4 / WW;

    const int ym = max(y-1,0)*WW, y0r = y*WW, yp = min(y+1,HH-1)*WW;
    const int xl = max(x-1,0), xr = min(x+4, WW-1);

    float f1v[2][4]; float jfb[2][4];
    #pragma unroll
    for (int j = 0; j < 2; ++j) {
        const float* F = F1 + (size_t)(b*CC + c2*2 + j)*HW;
        float rm[6], r0[6], rp[6];
        {
            float4 a = *(const float4*)(F + ym  + x);
            rm[0]=F[ym+xl]; rm[1]=a.x; rm[2]=a.y; rm[3]=a.z; rm[4]=a.w; rm[5]=F[ym+xr];
            float4 bq = *(const float4*)(F + y0r + x);
            r0[0]=F[y0r+xl]; r0[1]=bq.x; r0[2]=bq.y; r0[3]=bq.z; r0[4]=bq.w; r0[5]=F[y0r+xr];
            float4 c = *(const float4*)(F + yp  + x);
            rp[0]=F[yp+xl]; rp[1]=c.x; rp[2]=c.y; rp[3]=c.z; rp[4]=c.w; rp[5]=F[yp+xr];
        }
        #pragma unroll
        for (int k = 0; k < 4; ++k) {
            const float dx = (rm[k+2]-rm[k]) + 2.0f*(r0[k+2]-r0[k]) + (rp[k+2]-rp[k]);
            const float dy = (rp[k]-rm[k]) + 2.0f*(rp[k+1]-rm[k+1]) + (rp[k+2]-rm[k+2]);
            const float inv_mag = rsqrtf(dx*dx + dy*dy + 1e-8f);
            __half2 h = __floats2half2_rn(dx*inv_mag, dy*inv_mag);
            jfb[j][k] = __uint_as_float(*reinterpret_cast<unsigned*>(&h));
            f1v[j][k] = r0[k+1];
        }
    }
    Tap2* D = g_tap2 + (size_t)(b*NC2 + c2)*HW + i4;
    #pragma unroll
    for (int k = 0; k < 4; ++k)
        D[k] = make_float4(f1v[0][k], jfb[0][k], f1v[1][k], jfb[1][k]);
}

// ----- fused per-pixel accumulation + last-block reduction/solve -------------
__global__ void __launch_bounds__(256)
accum_kernel(const float* __restrict__ F0, const float* __restrict__ invD0,
             const float* __restrict__ invD1, const float* __restrict__ Kmat,
             float* __restrict__ out, int it)
{
    const int  b    = blockIdx.y;
    const int  last = (it == 2);
    const int  pix  = blockIdx.x*blockDim.x + threadIdx.x;   // 0..19199 exactly
    const int  x    = pix % WW;
    const int  y    = pix / WW;

    // pose + intrinsics (broadcast loads)
    const float R0=g_R[b][0], R1=g_R[b][1], R2=g_R[b][2];
    const float R3=g_R[b][3], R4=g_R[b][4], R5=g_R[b][5];
    const float R6=g_R[b][6], R7=g_R[b][7], R8=g_R[b][8];
    const float t0=g_t[b][0], t1=g_t[b][1], t2=g_t[b][2];
    const float fx=Kmat[b*4+0], fy=Kmat[b*4+1], cx=Kmat[b*4+2], cy=Kmat[b*4+3];

    const float px = ((float)x - cx) / fx;
    const float py = ((float)y - cy) / fy;
    const float id0 = invD0[(size_t)b*HW + pix];

    // warp inverse depth: warped = R*[px,py,1] + t*invD0
    const float X = R0*px + R1*py + R2 + t0*id0;
    const float Y = R3*px + R4*py + R5 + t1*id0;
    const float S = R6*px + R7*py + R8 + t2*id0;
    const float u = (X/S)*fx + cx;
    const float v = (Y/S)*fy + cy;
    const float inv_z = id0 / S;

    const bool inview = (u > 0.0f) && (u < (float)(WW-1)) &&
                        (v > 0.0f) && (v < (float)(HH-1));

    // clipped bilinear setup
    const float uc = fminf(fmaxf(u, 0.0f), (float)(WW-1));
    const float vc = fminf(fmaxf(v, 0.0f), (float)(HH-1));
    const float x0f = floorf(uc), y0f = floorf(vc);
    const float wx = uc - x0f,  wy = vc - y0f;
    const int x0 = (int)x0f, y0 = (int)y0f;
    const int x1 = min(x0+1, WW-1), y1 = min(y0+1, HH-1);
    const int i00 = y0*WW+x0, i01 = y0*WW+x1, i10 = y1*WW+x0, i11 = y1*WW+x1;
    const float w00 = (1.0f-wx)*(1.0f-wy), w01 = wx*(1.0f-wy);
    const float w10 = (1.0f-wx)*wy,        w11 = wx*wy;

    // occlusion (invD1 warp, single channel)
    const float* D1 = invD1 + (size_t)b*HW;
    const float invD1w = D1[i00]*w00 + D1[i01]*w01 + D1[i10]*w10 + D1[i11]*w11;
    const bool occ = !((inv_z > invD1w - OCC_THRES) && inview);

    // jacobian warp: warped = R*[px,py,invD0] + t
    const float xj = R0*px + R1*py + R2*id0 + t0;
    const float yj = R3*px + R4*py + R5*id0 + t1;
    const float iz = R6*px + R7*py + R8*id0 + t2;
    const float Jx[6] = { fx*(-xj*yj), fx*(1.0f+xj*xj), fx*(-yj),
                          fx*iz,       0.0f,            fx*(-iz*xj) };
    const float Jy[6] = { fy*(-1.0f-yj*yj), fy*(xj*yj), fy*xj,
                          0.0f,             fy*iz,      fy*(-iz*yj) };

    // channel-pair loop -> 5 scalar sums
    float saa = 0.f, sab = 0.f, sbb = 0.f, sar = 0.f, sbr = 0.f;
    const float* F0b = F0     + (size_t)b*CHW;
    const Tap2*  Tb  = g_tap2 + (size_t)b*NC2*HW;

    #pragma unroll 2
    for (int c2 = 0; c2 < NC2; ++c2) {
        const Tap2* T2 = Tb + (size_t)c2*HW;
        const Tap2 q00 = T2[i00];
        const Tap2 q01 = T2[i01];
        const Tap2 q10 = T2[i10];
        const Tap2 q11 = T2[i11];
        #pragma unroll
        for (int j = 0; j < 2; ++j) {
            const int o = (c2*2 + j)*HW;
            const float f00 = j ? q00.z : q00.x,  b00 = j ? q00.w : q00.y;
            const float f01 = j ? q01.z : q01.x,  b01 = j ? q01.w : q01.y;
            const float f10 = j ? q10.z : q10.x,  b10 = j ? q10.w : q10.y;
            const float f11 = j ? q11.z : q11.x,  b11 = j ? q11.w : q11.y;
            const float f1w = f00*w00 + f01*w01 + f10*w10 + f11*w11;
            const float2 g00 = jf_of(b00);
            const float2 g01 = jf_of(b01);
            const float2 g10 = jf_of(b10);
            const float2 g11 = jf_of(b11);
            const float ax = g00.x*w00 + g01.x*w01 + g10.x*w10 + g11.x*w11;
            const float ay = g00.y*w00 + g01.y*w01 + g10.y*w10 + g11.y*w11;
            const float r   = occ ? 0.001f : (f1w - F0b[o + pix]);
            const float wgt = __fdividef(1.0f, 1.0f + r*r);
            const float wr  = wgt * r;
            saa += ax*ax;  sab += ax*ay;  sbb += ay*ay;
            sar += ax*wr;  sbr += ay*wr;
            if (last) __stwt(&out[(size_t)b*OUT_ROW + 12 + o + pix], wgt);
        }
    }

    // per-pixel contribution: 21 (upper-tri 6x6) + 6 (rhs)
    float acc[27];
    {
        int idx = 0;
        #pragma unroll
        for (int k = 0; k < 6; ++k)
            #pragma unroll
            for (int l = k; l < 6; ++l)
                acc[idx++] = saa*Jx[k]*Jx[l] + sab*(Jx[k]*Jy[l] + Jy[k]*Jx[l])
                           + sbb*Jy[k]*Jy[l];
        #pragma unroll
        for (int k = 0; k < 6; ++k)
            acc[idx++] = -(sar*Jx[k] + sbr*Jy[k]);
    }

    // deterministic block reduction: warp shuffle -> smem -> single partial
    #pragma unroll
    for (int j = 0; j < 27; ++j) {
        float s = acc[j];
        #pragma unroll
        for (int off = 16; off > 0; off >>= 1)
            s += __shfl_down_sync(0xffffffffu, s, off);
        acc[j] = s;
    }
    __shared__ float sm[8][27];
    const int warp = threadIdx.x >> 5, lane = threadIdx.x & 31;
    if (lane == 0) {
        #pragma unroll
        for (int j = 0; j < 27; ++j) sm[warp][j] = acc[j];
    }
    __syncthreads();
    if (threadIdx.x < 27) {
        float s = 0.f;
        #pragma unroll
        for (int wp = 0; wp < 8; ++wp) s += sm[wp][threadIdx.x];
        g_part[b][blockIdx.x][threadIdx.x] = s;
    }

    // ---------- last-arriving block for this batch does reduce + solve -------
    __syncthreads();                       // g_part stores complete block-wide
    __shared__ int amLast;
    __threadfence();                       // publish g_part slice
    if (threadIdx.x == 0)
        amLast = (atomicAdd(&g_cnt[it][b], 1) == NBLK - 1);
    __syncthreads();
    if (!amLast) return;
    __threadfence();                       // acquire other blocks' g_part

    __shared__ float red[27];
    if (threadIdx.x < 27) {
        double s0 = 0.0, s1 = 0.0, s2 = 0.0, s3 = 0.0, s4 = 0.0;
        #pragma unroll
        for (int i = 0; i < 15; ++i) {
            s0 += (double)g_part[b][i     ][threadIdx.x];
            s1 += (double)g_part[b][i + 15][threadIdx.x];
            s2 += (double)g_part[b][i + 30][threadIdx.x];
            s3 += (double)g_part[b][i + 45][threadIdx.x];
            s4 += (double)g_part[b][i + 60][threadIdx.x];
        }
        red[threadIdx.x] = (float)(((s0 + s1) + (s2 + s3)) + s4);
    }
    __syncthreads();
    if (threadIdx.x != 0) return;

    g_cnt[it][b] = 0;                      // reset for next graph replay

    // assemble SPD A (+damping) and rhs  (fp32)
    float A[6][6], rhs[6];
    {
        int idx = 0;
        #pragma unroll
        for (int k = 0; k < 6; ++k)
            #pragma unroll
            for (int l = 0; l < 6; ++l) if (l >= k) { A[k][l] = red[idx]; A[l][k] = red[idx]; ++idx; }
        #pragma unroll
        for (int k = 0; k < 6; ++k) A[k][k] += 1e-4f;
        #pragma unroll
        for (int i = 0; i < 6; ++i) rhs[i] = red[21+i];
    }

    // Cholesky A = L L^T (SPD, no pivoting) — accurate fp32 ops
    float L[6][6];
    #pragma unroll
    for (int j = 0; j < 6; ++j) {
        float d = A[j][j];
        #pragma unroll
        for (int k = 0; k < 6; ++k) if (k < j) d -= L[j][k]*L[j][k];
        const float ljj = sqrtf(d);
        const float inv_ljj = 1.0f / ljj;
        L[j][j] = ljj;
        #pragma unroll
        for (int i = 0; i < 6; ++i) if (i > j) {
            float s = A[i][j];
            #pragma unroll
            for (int k = 0; k < 6; ++k) if (k < j) s -= L[i][k]*L[j][k];
            L[i][j] = s * inv_ljj;
        }
    }
    // forward/back substitution
    float yv[6], dp[6];
    #pragma unroll
    for (int i = 0; i < 6; ++i) {
        float s = rhs[i];
        #pragma unroll
        for (int k = 0; k < 6; ++k) if (k < i) s -= L[i][k]*yv[k];
        yv[i] = s / L[i][i];
    }
    #pragma unroll
    for (int i = 5; i >= 0; --i) {
        float s = yv[i];
        #pragma unroll
        for (int k = 0; k < 6; ++k) if (k > i) s -= L[k][i]*dp[k];
        dp[i] = s / L[i][i];
    }

    // se3 exponential (fp32, accurate sincosf/sqrtf)
    const float w0 = dp[0], w1 = dp[1], w2 = dp[2];
    const float v0 = dp[3], v1 = dp[4], v2 = dp[5];
    const float th2  = w0*w0 + w1*w1 + w2*w2;
    const float th2e = th2 + 1e-12f;
    const float th   = sqrtf(th2e);
    float sth, cth;
    sincosf(th, &sth, &cth);
    const float a   = sth / th;
    const float bbv = (1.0f - cth) / th2e;
    const float ccv = (1.0f - a) / th2e;
    const float Wm[3][3] = { {0.0f, -w2,  w1},
                             {w2,  0.0f, -w0},
                             {-w1, w0,  0.0f} };
    float W2[3][3];
    #pragma unroll
    for (int i = 0; i < 3; ++i)
        #pragma unroll
        for (int j = 0; j < 3; ++j)
            W2[i][j] = Wm[i][0]*Wm[0][j] + Wm[i][1]*Wm[1][j] + Wm[i][2]*Wm[2][j];
    float dR[3][3], Vm[3][3];
    #pragma unroll
    for (int i = 0; i < 3; ++i)
        #pragma unroll
        for (int j = 0; j < 3; ++j) {
            const float I = (i == j) ? 1.0f : 0.0f;
            dR[i][j] = I + a  * Wm[i][j] + bbv * W2[i][j];
            Vm[i][j] = I + bbv* Wm[i][j] + ccv * W2[i][j];
        }
    const float dt0 = Vm[0][0]*v0 + Vm[0][1]*v1 + Vm[0][2]*v2;
    const float dt1 = Vm[1][0]*v0 + Vm[1][1]*v1 + Vm[1][2]*v2;
    const float dt2 = Vm[2][0]*v0 + Vm[2][1]*v1 + Vm[2][2]*v2;

    // pose update: t = dR*t + dt ; R = dR*R
    float Rold[9], told[3];
    #pragma unroll
    for (int i = 0; i < 9; ++i) Rold[i] = g_R[b][i];
    #pragma unroll
    for (int i = 0; i < 3; ++i) told[i] = g_t[b][i];

    float tnew[3], Rnew[9];
    #pragma unroll
    for (int i = 0; i < 3; ++i) {
        tnew[i] = dR[i][0]*told[0] + dR[i][1]*told[1] + dR[i][2]*told[2]
                + ((i==0)?dt0:(i==1)?dt1:dt2);
        #pragma unroll
        for (int j = 0; j < 3; ++j)
            Rnew[i*3+j] = dR[i][0]*Rold[0*3+j] + dR[i][1]*Rold[1*3+j] + dR[i][2]*Rold[2*3+j];
    }
    #pragma unroll
    for (int i = 0; i < 9; ++i) g_R[b][i] = Rnew[i];
    #pragma unroll
    for (int i = 0; i < 3; ++i) g_t[b][i] = tnew[i];

    if (last) {
        #pragma unroll
        for (int i = 0; i < 9; ++i) out[(size_t)b*OUT_ROW + i]     = Rnew[i];
        #pragma unroll
        for (int i = 0; i < 3; ++i) out[(size_t)b*OUT_ROW + 9 + i] = tnew[i];
    }
}

// ---------------- launch ------------------------------------------------------
extern "C" void kernel_launch(void* const* d_in, const int* in_sizes, int n_in,
                              void* d_out, int out_size) {
    const float* R     = (const float*)d_in[0];
    const float* t     = (const float*)d_in[1];
    const float* F0    = (const float*)d_in[2];
    const float* F1    = (const float*)d_in[3];
    const float* invD0 = (const float*)d_in[4];
    const float* invD1 = (const float*)d_in[5];
    const float* K     = (const float*)d_in[6];
    float* out = (float*)d_out;

    const int nth = BB*NC2*(HW/4);
    sobel_kernel<<<(nth + 255)/256, 256>>>(F1, R, t);

    for (int it = 0; it < 3; ++it)
        accum_kernel<<<dim3(NBLK, BB), 256>>>(F0, invD0, invD1, K, out, it);
}